// round 15
// baseline (speedup 1.0000x reference)
#include <cuda_runtime.h>
#include <cuda_fp16.h>
#include <cstdint>

#define NPTS 262144
#define DPBLKS 6144   // 3*NPTS/128
#define ICBLKS 2048   // NPTS/128

// ---------------- scratch (__device__ globals; no allocation allowed) -----
__device__ float g_feats[NPTS * 8];   // [r, ux, uy, uz, inv, a, 0, 0]
__device__ float g_ic[NPTS];
__device__ float g_dp[NPTS * 3];

// Input layer B frags (3-product split, weights pre-scaled 2^10):
//   per MLP 16 frags x 32 lanes, uint4 {h0, h1, l0, l1}
__device__ uint4 g_WpIn[2 * 512];
// Hidden layer B frags (single fp16, unscaled), two n8 frags per uint4:
//   per MLP 24 ksteps x 8 jpairs x 32 lanes, uint4 {j0b0, j0b1, j1b0, j1b1}
__device__ uint4 g_WpH[2 * 6144];

__constant__ float c_np1[3] = {1.0f - 0.7745966692f, 1.0f, 1.0f + 0.7745966692f};

#define WSI 0.0009765625f   // 2^-10: undo input-layer weight pre-scale

// ---------------- math helpers --------------------------------------------
// single-instruction HW tanh (MUFU), fp32
__device__ __forceinline__ float fast_tanh(float x) {
    float t;
    asm("tanh.approx.f32 %0, %1;" : "=f"(t) : "f"(x));
    return t;
}
// packed fp16x2 HW tanh — 2 activations per MUFU op
__device__ __forceinline__ uint32_t tanh_h2(uint32_t x) {
    uint32_t t;
    asm("tanh.approx.f16x2 %0, %1;" : "=r"(t) : "r"(x));
    return t;
}
// pack two floats into fp16x2 (v0 -> low half)
__device__ __forceinline__ uint32_t pack_h2(float v0, float v1) {
    uint32_t u;
    asm("cvt.rn.f16x2.f32 %0, %1, %2;" : "=r"(u) : "f"(v1), "f"(v0));
    return u;
}
// bias-add in fp32, pack to fp16x2, packed tanh -> ready A fragment
__device__ __forceinline__ uint32_t act_pack(float v0, float v1) {
    return tanh_h2(pack_h2(v0, v1));
}
// split (v0,v1) into fp16x2 hi + fp16x2 residual lo
__device__ __forceinline__ void split2h(float v0, float v1,
                                        uint32_t& uh, uint32_t& ul) {
    __half h0 = __float2half_rn(v0), h1 = __float2half_rn(v1);
    __half l0 = __float2half_rn(v0 - __half2float(h0));
    __half l1 = __float2half_rn(v1 - __half2float(h1));
    uh = (uint32_t)__half_as_ushort(h0) | ((uint32_t)__half_as_ushort(h1) << 16);
    ul = (uint32_t)__half_as_ushort(l0) | ((uint32_t)__half_as_ushort(l1) << 16);
}

// fp16 HMMA k16: D(16x8) += A(16x16) * B(16x8), fp32 accum
__device__ __forceinline__ void mma16816(float c[4], uint32_t a0, uint32_t a1,
                                         uint32_t a2, uint32_t a3,
                                         uint32_t b0, uint32_t b1) {
    asm volatile(
        "mma.sync.aligned.m16n8k16.row.col.f32.f16.f16.f32 "
        "{%0,%1,%2,%3}, {%4,%5,%6,%7}, {%8,%9}, {%0,%1,%2,%3};"
        : "+f"(c[0]), "+f"(c[1]), "+f"(c[2]), "+f"(c[3])
        : "r"(a0), "r"(a1), "r"(a2), "r"(a3), "r"(b0), "r"(b1));
}
// fp16 HMMA k8 (input layer)
__device__ __forceinline__ void mma1688(float c[4], uint32_t a0, uint32_t a1,
                                        uint32_t b0) {
    asm volatile(
        "mma.sync.aligned.m16n8k8.row.col.f32.f16.f16.f32 "
        "{%0,%1,%2,%3}, {%4,%5}, {%6}, {%0,%1,%2,%3};"
        : "+f"(c[0]), "+f"(c[1]), "+f"(c[2]), "+f"(c[3])
        : "r"(a0), "r"(a1), "r"(b0));
}

// ---------------- kernel 1: per-point features ----------------------------
__global__ void prep_kernel(const float4* __restrict__ tx) {
    int i = blockIdx.x * blockDim.x + threadIdx.x;
    if (i >= NPTS) return;
    float4 v = tx[i];
    float r = sqrtf(v.y * v.y + v.z * v.z + v.w * v.w);
    float rs = fmaxf(r, 1e-8f);
    float inv = 1.0f / (1.0f + r);
    float a = v.x * 0.5f;   // T0 = 0; CLIP = 1 -> min(r, max r) == r
    float* o = g_feats + i * 8;
    ((float4*)o)[0] = make_float4(r, v.y / rs, v.z / rs, v.w / rs);
    ((float4*)o)[1] = make_float4(inv, a, 0.f, 0.f);
}

// ---------------- kernel 2: pack weights ----------------------------------
__global__ void wprep_kernel(const float* __restrict__ dp_Win,
                             const float* __restrict__ dp_Wh,
                             const float* __restrict__ ic_Win,
                             const float* __restrict__ ic_Wh) {
    int t = blockIdx.x * blockDim.x + threadIdx.x;
    if (t < 1024) {
        // ---- input layer: hi/lo split, weights x 2^10 ----
        int m = t >> 9;                 // 0 = dp, 1 = ic
        int e = t & 511;
        int J = e >> 5, lane = e & 31;
        const float* Win = m ? ic_Win : dp_Win;
        int din = m ? 5 : 6;
        int q = lane & 3;
        int n = J * 8 + (lane >> 2);
        int k0 = 2 * q;
        float w00 = (k0     < din) ? Win[k0 * 128 + n]       : 0.f;
        float w01 = (k0 + 1 < din) ? Win[(k0 + 1) * 128 + n] : 0.f;
        uint32_t h0, l0;
        split2h(w00 * 1024.0f, w01 * 1024.0f, h0, l0);
        g_WpIn[t] = make_uint4(h0, 0u, l0, 0u);
        return;
    }
    int t2 = t - 1024;
    if (t2 >= 2 * 6144) return;
    // ---- hidden layers: single fp16, two j-frags per uint4 ----
    int m = t2 / 6144;
    int e = t2 - m * 6144;
    int lane = e & 31;
    int jp = (e >> 5) & 7;
    int ks = e >> 8;                    // 0..23
    int l = ks >> 3, s = ks & 7;
    const float* W = (m ? ic_Wh : dp_Wh) + l * 16384;
    int q = lane & 3;
    int kb = 16 * s + 2 * q;
    int nrow = lane >> 2;

    int n0 = (2 * jp) * 8 + nrow;
    uint32_t j0b0 = pack_h2(W[kb * 128 + n0],       W[(kb + 1) * 128 + n0]);
    uint32_t j0b1 = pack_h2(W[(kb + 8) * 128 + n0], W[(kb + 9) * 128 + n0]);
    int n1 = (2 * jp + 1) * 8 + nrow;
    uint32_t j1b0 = pack_h2(W[kb * 128 + n1],       W[(kb + 1) * 128 + n1]);
    uint32_t j1b1 = pack_h2(W[(kb + 8) * 128 + n1], W[(kb + 9) * 128 + n1]);
    g_WpH[t2] = make_uint4(j0b0, j0b1, j1b0, j1b1);
}

// ---------------- input A-fragment builder (fp16 split) --------------------
__device__ __forceinline__ void build_in(bool isdp, int grow, int q,
                                         uint32_t& ah, uint32_t& al) {
    float xa, xb;
    if (isdp) {
        int p = grow / 3, nd = grow - 3 * p;
        float4 f0 = *(const float4*)(g_feats + p * 8);       // r ux uy uz
        float2 f1 = *(const float2*)(g_feats + p * 8 + 4);   // inv a
        float tt = f1.y * c_np1[nd];
        xa = (q == 0) ? tt   : (q == 1) ? f0.y : (q == 2) ? f0.w : 0.f;
        xb = (q == 0) ? f0.x : (q == 1) ? f0.z : (q == 2) ? f1.x : 0.f;
    } else {
        float4 f0 = *(const float4*)(g_feats + grow * 8);
        float2 f1 = *(const float2*)(g_feats + grow * 8 + 4);
        xa = (q == 0) ? f0.x : (q == 1) ? f0.z : (q == 2) ? f1.x : 0.f;
        xb = (q == 0) ? f0.y : (q == 1) ? f0.w : 0.f;
    }
    split2h(xa, xb, ah, al);
}

// ---------------- one pipelined hidden layer -------------------------------
// Consumes Cold (pre-activations of previous layer), produces Cnew.
// Epilogue for k-step s+1 (bias fp32-add, pack, packed f16x2 tanh) is
// interleaved with the HMMAs of k-step s.
__device__ __forceinline__ void hidden_layer(
    const float (&Cold)[16][4], float (&Cnew)[16][4],
    const float* __restrict__ biasl, float sc,
    const uint4* __restrict__ BL, int lane, int q) {
#pragma unroll
    for (int j = 0; j < 16; j++) {
        Cnew[j][0] = 0.f; Cnew[j][1] = 0.f; Cnew[j][2] = 0.f; Cnew[j][3] = 0.f;
    }
    uint32_t A0, A1, A2, A3;
    {   // epilogue for s = 0 (j = 0,1)
        float2 b0 = *(const float2*)(biasl + 0 * 8 + 2 * q);
        float2 b1 = *(const float2*)(biasl + 1 * 8 + 2 * q);
        A0 = act_pack(fmaf(Cold[0][0], sc, b0.x), fmaf(Cold[0][1], sc, b0.y));
        A1 = act_pack(fmaf(Cold[0][2], sc, b0.x), fmaf(Cold[0][3], sc, b0.y));
        A2 = act_pack(fmaf(Cold[1][0], sc, b1.x), fmaf(Cold[1][1], sc, b1.y));
        A3 = act_pack(fmaf(Cold[1][2], sc, b1.x), fmaf(Cold[1][3], sc, b1.y));
    }
#pragma unroll
    for (int s = 0; s < 8; s++) {
        uint32_t N0 = 0, N1 = 0, N2 = 0, N3 = 0;
        if (s < 7) {   // epilogue for s+1 — independent of this step's MMAs
            float2 b0 = *(const float2*)(biasl + (2 * s + 2) * 8 + 2 * q);
            float2 b1 = *(const float2*)(biasl + (2 * s + 3) * 8 + 2 * q);
            N0 = act_pack(fmaf(Cold[2 * s + 2][0], sc, b0.x),
                          fmaf(Cold[2 * s + 2][1], sc, b0.y));
            N1 = act_pack(fmaf(Cold[2 * s + 2][2], sc, b0.x),
                          fmaf(Cold[2 * s + 2][3], sc, b0.y));
            N2 = act_pack(fmaf(Cold[2 * s + 3][0], sc, b1.x),
                          fmaf(Cold[2 * s + 3][1], sc, b1.y));
            N3 = act_pack(fmaf(Cold[2 * s + 3][2], sc, b1.x),
                          fmaf(Cold[2 * s + 3][3], sc, b1.y));
        }
        const uint4* bp = &BL[s * 256 + lane];
#pragma unroll
        for (int jp = 0; jp < 8; jp++) {
            uint4 b = __ldg(bp + jp * 32);
            mma16816(Cnew[2 * jp],     A0, A1, A2, A3, b.x, b.y);
            mma16816(Cnew[2 * jp + 1], A0, A1, A2, A3, b.z, b.w);
        }
        A0 = N0; A1 = N1; A2 = N2; A3 = N3;
    }
}

// ---------------- kernel 3: pipelined fp16 HMMA MLP ------------------------
__global__ void __launch_bounds__(256, 1) mlp_mma(
    const float* __restrict__ dp_bin, const float* __restrict__ dp_bh,
    const float* __restrict__ dp_Wout, const float* __restrict__ dp_bout,
    const float* __restrict__ ic_bin, const float* __restrict__ ic_bh,
    const float* __restrict__ ic_Wout, const float* __restrict__ ic_bout) {
    __shared__ __align__(8) float sbias[512];
    __shared__ __align__(8) float swout[128];
    const bool isdp = blockIdx.x < DPBLKS;
    const int rowblk = isdp ? blockIdx.x : (blockIdx.x - DPBLKS);
    const float* bin  = isdp ? dp_bin  : ic_bin;
    const float* bh   = isdp ? dp_bh   : ic_bh;
    const float* Wout = isdp ? dp_Wout : ic_Wout;
    const float* bout = isdp ? dp_bout : ic_bout;

    const int tid = threadIdx.x, w = tid >> 5, lane = tid & 31;
    const int q = lane & 3, nr = lane >> 2;

    if (tid < 128) {
        sbias[tid]       = bin[tid];
        sbias[128 + tid] = bh[tid];
        sbias[256 + tid] = bh[128 + tid];
        sbias[384 + tid] = bh[256 + tid];
        swout[tid]       = Wout[tid];
    }
    __syncthreads();

    const int r0 = rowblk * 128 + w * 16 + nr;   // this thread: rows r0, r0+8
    const uint4* __restrict__ BpIn = g_WpIn + (isdp ? 0 : 1) * 512;
    const uint4* __restrict__ BpH  = g_WpH  + (isdp ? 0 : 1) * 6144;

    float CA[16][4], CB[16][4];
#pragma unroll
    for (int j = 0; j < 16; j++) {
        CA[j][0] = 0.f; CA[j][1] = 0.f; CA[j][2] = 0.f; CA[j][3] = 0.f;
    }

    // ---- input layer: k8, 3-product fp16 split -> CA (pre-acts x 2^10) ----
    {
        uint32_t a0h, a0l, a1h, a1l;
        build_in(isdp, r0, q, a0h, a0l);
        build_in(isdp, r0 + 8, q, a1h, a1l);
#pragma unroll
        for (int jg = 0; jg < 4; jg++) {
            uint4 b0 = __ldg(&BpIn[(jg * 4 + 0) * 32 + lane]);
            uint4 b1 = __ldg(&BpIn[(jg * 4 + 1) * 32 + lane]);
            uint4 b2 = __ldg(&BpIn[(jg * 4 + 2) * 32 + lane]);
            uint4 b3 = __ldg(&BpIn[(jg * 4 + 3) * 32 + lane]);
            mma1688(CA[jg * 4 + 0], a0h, a1h, b0.x);
            mma1688(CA[jg * 4 + 1], a0h, a1h, b1.x);
            mma1688(CA[jg * 4 + 2], a0h, a1h, b2.x);
            mma1688(CA[jg * 4 + 3], a0h, a1h, b3.x);
            mma1688(CA[jg * 4 + 0], a0h, a1h, b0.z);
            mma1688(CA[jg * 4 + 1], a0h, a1h, b1.z);
            mma1688(CA[jg * 4 + 2], a0h, a1h, b2.z);
            mma1688(CA[jg * 4 + 3], a0h, a1h, b3.z);
            mma1688(CA[jg * 4 + 0], a0l, a1l, b0.x);
            mma1688(CA[jg * 4 + 1], a0l, a1l, b1.x);
            mma1688(CA[jg * 4 + 2], a0l, a1l, b2.x);
            mma1688(CA[jg * 4 + 3], a0l, a1l, b3.x);
        }
    }

    // ---- 3 pipelined hidden layers ----
    hidden_layer(CA, CB, sbias,       WSI,  BpH,        lane, q);
    hidden_layer(CB, CA, sbias + 128, 1.0f, BpH + 2048, lane, q);
    hidden_layer(CA, CB, sbias + 256, 1.0f, BpH + 4096, lane, q);

    // ---- final: bias + fp32 tanh + dot(Wout) + quad reduce ----
    float s0 = 0.f, s1 = 0.f;
#pragma unroll
    for (int j = 0; j < 16; j++) {
        float2 bb = *(const float2*)(sbias + 384 + j * 8 + 2 * q);
        float2 ww = *(const float2*)(swout + j * 8 + 2 * q);
        s0 = fmaf(fast_tanh(CB[j][0] + bb.x), ww.x, s0);
        s0 = fmaf(fast_tanh(CB[j][1] + bb.y), ww.y, s0);
        s1 = fmaf(fast_tanh(CB[j][2] + bb.x), ww.x, s1);
        s1 = fmaf(fast_tanh(CB[j][3] + bb.y), ww.y, s1);
    }
    s0 += __shfl_xor_sync(0xffffffffu, s0, 1);
    s0 += __shfl_xor_sync(0xffffffffu, s0, 2);
    s1 += __shfl_xor_sync(0xffffffffu, s1, 1);
    s1 += __shfl_xor_sync(0xffffffffu, s1, 2);
    if (q == 0) {
        float bo = __ldg(bout);
        float* gout = isdp ? g_dp : g_ic;
        gout[r0]     = s0 + bo;
        gout[r0 + 8] = s1 + bo;
    }
}

// ---------------- kernel 4: GL quadrature + final scaling ------------------
__global__ void combine_kernel(float* __restrict__ out) {
    int i = blockIdx.x * blockDim.x + threadIdx.x;
    if (i >= NPTS) return;
    const float* f = g_feats + i * 8;
    float a = f[5], inv = f[4];
    const float w0 = (float)(5.0 / 9.0), w1 = (float)(8.0 / 9.0);
    float s = w0 * g_dp[3 * i] + w1 * g_dp[3 * i + 1] + w0 * g_dp[3 * i + 2];
    out[i] = (g_ic[i] + a * s) * inv;
}

// ---------------- host launcher --------------------------------------------
extern "C" void kernel_launch(void* const* d_in, const int* in_sizes, int n_in,
                              void* d_out, int out_size) {
    const float* tx      = (const float*)d_in[0];
    const float* dp_Win  = (const float*)d_in[1];
    const float* dp_bin  = (const float*)d_in[2];
    const float* dp_Wh   = (const float*)d_in[3];
    const float* dp_bh   = (const float*)d_in[4];
    const float* dp_Wout = (const float*)d_in[5];
    const float* dp_bout = (const float*)d_in[6];
    const float* ic_Win  = (const float*)d_in[7];
    const float* ic_bin  = (const float*)d_in[8];
    const float* ic_Wh   = (const float*)d_in[9];
    const float* ic_bh   = (const float*)d_in[10];
    const float* ic_Wout = (const float*)d_in[11];
    const float* ic_bout = (const float*)d_in[12];
    float* out = (float*)d_out;

    prep_kernel<<<NPTS / 256, 256>>>((const float4*)tx);
    wprep_kernel<<<(1024 + 2 * 6144 + 255) / 256, 256>>>(dp_Win, dp_Wh,
                                                         ic_Win, ic_Wh);
    mlp_mma<<<DPBLKS + ICBLKS, 256>>>(dp_bin, dp_bh, dp_Wout, dp_bout,
                                      ic_bin, ic_bh, ic_Wout, ic_bout);
    combine_kernel<<<NPTS / 256, 256>>>(out);
}

// round 16
// speedup vs baseline: 1.0251x; 1.0251x over previous
#include <cuda_runtime.h>
#include <cuda_fp16.h>
#include <cstdint>

#define NPTS 262144
#define DPBLKS 6144   // 3*NPTS/128
#define ICBLKS 2048   // NPTS/128

// ---------------- scratch (__device__ globals; no allocation allowed) -----
__device__ float g_feats[NPTS * 8];   // [r, ux, uy, uz, inv, a, 0, 0]
__device__ float g_ic[NPTS];
__device__ float g_dp[NPTS * 3];

// Input layer B frags (3-product split, weights pre-scaled 2^10):
//   per MLP 16 frags x 32 lanes, uint4 {h0, h1, l0, l1}
__device__ uint4 g_WpIn[2 * 512];
// Hidden layer B frags (single fp16, unscaled), two n8 frags per uint4:
//   per MLP 24 ksteps x 8 jpairs x 32 lanes, uint4 {j0b0, j0b1, j1b0, j1b1}
__device__ uint4 g_WpH[2 * 6144];

__constant__ float c_np1[3] = {1.0f - 0.7745966692f, 1.0f, 1.0f + 0.7745966692f};

#define WSI 0.0009765625f   // 2^-10: undo input-layer pre-scale (W and bias)

// ---------------- math helpers --------------------------------------------
// single-instruction HW tanh (MUFU), fp32 — R14-validated accuracy
__device__ __forceinline__ float fast_tanh(float x) {
    float t;
    asm("tanh.approx.f32 %0, %1;" : "=f"(t) : "f"(x));
    return t;
}
template <bool SC>
__device__ __forceinline__ float presc(float x) { return SC ? x * WSI : x; }
// pack two floats into fp16x2 (v0 -> low half)
__device__ __forceinline__ uint32_t pack_h2(float v0, float v1) {
    uint32_t u;
    asm("cvt.rn.f16x2.f32 %0, %1, %2;" : "=r"(u) : "f"(v1), "f"(v0));
    return u;
}
// split (v0,v1) into fp16x2 hi + fp16x2 residual lo
__device__ __forceinline__ void split2h(float v0, float v1,
                                        uint32_t& uh, uint32_t& ul) {
    __half h0 = __float2half_rn(v0), h1 = __float2half_rn(v1);
    __half l0 = __float2half_rn(v0 - __half2float(h0));
    __half l1 = __float2half_rn(v1 - __half2float(h1));
    uh = (uint32_t)__half_as_ushort(h0) | ((uint32_t)__half_as_ushort(h1) << 16);
    ul = (uint32_t)__half_as_ushort(l0) | ((uint32_t)__half_as_ushort(l1) << 16);
}

// fp16 HMMA k16: D(16x8) += A(16x16) * B(16x8), fp32 accum
__device__ __forceinline__ void mma16816(float c[4], uint32_t a0, uint32_t a1,
                                         uint32_t a2, uint32_t a3,
                                         uint32_t b0, uint32_t b1) {
    asm volatile(
        "mma.sync.aligned.m16n8k16.row.col.f32.f16.f16.f32 "
        "{%0,%1,%2,%3}, {%4,%5,%6,%7}, {%8,%9}, {%0,%1,%2,%3};"
        : "+f"(c[0]), "+f"(c[1]), "+f"(c[2]), "+f"(c[3])
        : "r"(a0), "r"(a1), "r"(a2), "r"(a3), "r"(b0), "r"(b1));
}
// fp16 HMMA k8 (input layer)
__device__ __forceinline__ void mma1688(float c[4], uint32_t a0, uint32_t a1,
                                        uint32_t b0) {
    asm volatile(
        "mma.sync.aligned.m16n8k8.row.col.f32.f16.f16.f32 "
        "{%0,%1,%2,%3}, {%4,%5}, {%6}, {%0,%1,%2,%3};"
        : "+f"(c[0]), "+f"(c[1]), "+f"(c[2]), "+f"(c[3])
        : "r"(a0), "r"(a1), "r"(b0));
}

// ---------------- kernel 1: per-point features ----------------------------
__global__ void prep_kernel(const float4* __restrict__ tx) {
    int i = blockIdx.x * blockDim.x + threadIdx.x;
    if (i >= NPTS) return;
    float4 v = tx[i];
    float r = sqrtf(v.y * v.y + v.z * v.z + v.w * v.w);
    float rs = fmaxf(r, 1e-8f);
    float inv = 1.0f / (1.0f + r);
    float a = v.x * 0.5f;   // T0 = 0; CLIP = 1 -> min(r, max r) == r
    float* o = g_feats + i * 8;
    ((float4*)o)[0] = make_float4(r, v.y / rs, v.z / rs, v.w / rs);
    ((float4*)o)[1] = make_float4(inv, a, 0.f, 0.f);
}

// ---------------- kernel 2: pack weights ----------------------------------
__global__ void wprep_kernel(const float* __restrict__ dp_Win,
                             const float* __restrict__ dp_Wh,
                             const float* __restrict__ ic_Win,
                             const float* __restrict__ ic_Wh) {
    int t = blockIdx.x * blockDim.x + threadIdx.x;
    if (t < 1024) {
        // ---- input layer: hi/lo split, weights x 2^10 ----
        int m = t >> 9;                 // 0 = dp, 1 = ic
        int e = t & 511;
        int J = e >> 5, lane = e & 31;
        const float* Win = m ? ic_Win : dp_Win;
        int din = m ? 5 : 6;
        int q = lane & 3;
        int n = J * 8 + (lane >> 2);
        int k0 = 2 * q;
        float w00 = (k0     < din) ? Win[k0 * 128 + n]       : 0.f;
        float w01 = (k0 + 1 < din) ? Win[(k0 + 1) * 128 + n] : 0.f;
        uint32_t h0, l0;
        split2h(w00 * 1024.0f, w01 * 1024.0f, h0, l0);
        g_WpIn[t] = make_uint4(h0, 0u, l0, 0u);
        return;
    }
    int t2 = t - 1024;
    if (t2 >= 2 * 6144) return;
    // ---- hidden layers: single fp16, two j-frags per uint4 ----
    int m = t2 / 6144;
    int e = t2 - m * 6144;
    int lane = e & 31;
    int jp = (e >> 5) & 7;
    int ks = e >> 8;                    // 0..23
    int l = ks >> 3, s = ks & 7;
    const float* W = (m ? ic_Wh : dp_Wh) + l * 16384;
    int q = lane & 3;
    int kb = 16 * s + 2 * q;
    int nrow = lane >> 2;

    int n0 = (2 * jp) * 8 + nrow;
    uint32_t j0b0 = pack_h2(W[kb * 128 + n0],       W[(kb + 1) * 128 + n0]);
    uint32_t j0b1 = pack_h2(W[(kb + 8) * 128 + n0], W[(kb + 9) * 128 + n0]);
    int n1 = (2 * jp + 1) * 8 + nrow;
    uint32_t j1b0 = pack_h2(W[kb * 128 + n1],       W[(kb + 1) * 128 + n1]);
    uint32_t j1b1 = pack_h2(W[(kb + 8) * 128 + n1], W[(kb + 9) * 128 + n1]);
    g_WpH[t2] = make_uint4(j0b0, j0b1, j1b0, j1b1);
}

// ---------------- input A-fragment builder (fp16 split) --------------------
__device__ __forceinline__ void build_in(bool isdp, int grow, int q,
                                         uint32_t& ah, uint32_t& al) {
    float xa, xb;
    if (isdp) {
        int p = grow / 3, nd = grow - 3 * p;
        float4 f0 = *(const float4*)(g_feats + p * 8);       // r ux uy uz
        float2 f1 = *(const float2*)(g_feats + p * 8 + 4);   // inv a
        float tt = f1.y * c_np1[nd];
        xa = (q == 0) ? tt   : (q == 1) ? f0.y : (q == 2) ? f0.w : 0.f;
        xb = (q == 0) ? f0.x : (q == 1) ? f0.z : (q == 2) ? f1.x : 0.f;
    } else {
        float4 f0 = *(const float4*)(g_feats + grow * 8);
        float2 f1 = *(const float2*)(g_feats + grow * 8 + 4);
        xa = (q == 0) ? f0.x : (q == 1) ? f0.z : (q == 2) ? f1.x : 0.f;
        xb = (q == 0) ? f0.y : (q == 1) ? f0.w : 0.f;
    }
    split2h(xa, xb, ah, al);
}

// ---------------- one pipelined hidden layer -------------------------------
// Cold already CONTAINS its layer's bias (accumulator-initialized), so the
// epilogue is a bare tanh (+2^-10 unscale for the input layer, SC=true).
// Cnew is initialized with the NEXT layer's bias (bnext) instead of zero.
// Epilogue for k-step s+1 is interleaved with the HMMAs of k-step s.
template <bool SC>
__device__ __forceinline__ void hidden_layer(
    const float (&Cold)[16][4], float (&Cnew)[16][4],
    const float* __restrict__ bnext,
    const uint4* __restrict__ BL, int lane, int q) {
#pragma unroll
    for (int j = 0; j < 16; j++) {
        float2 bb = *(const float2*)(bnext + j * 8 + 2 * q);
        Cnew[j][0] = bb.x; Cnew[j][1] = bb.y;
        Cnew[j][2] = bb.x; Cnew[j][3] = bb.y;
    }
    uint32_t A0, A1, A2, A3;
    {   // epilogue for s = 0 (j = 0,1)
        A0 = pack_h2(fast_tanh(presc<SC>(Cold[0][0])),
                     fast_tanh(presc<SC>(Cold[0][1])));
        A1 = pack_h2(fast_tanh(presc<SC>(Cold[0][2])),
                     fast_tanh(presc<SC>(Cold[0][3])));
        A2 = pack_h2(fast_tanh(presc<SC>(Cold[1][0])),
                     fast_tanh(presc<SC>(Cold[1][1])));
        A3 = pack_h2(fast_tanh(presc<SC>(Cold[1][2])),
                     fast_tanh(presc<SC>(Cold[1][3])));
    }
#pragma unroll
    for (int s = 0; s < 8; s++) {
        uint32_t N0 = 0, N1 = 0, N2 = 0, N3 = 0;
        if (s < 7) {   // epilogue for s+1 — independent of this step's MMAs
            N0 = pack_h2(fast_tanh(presc<SC>(Cold[2 * s + 2][0])),
                         fast_tanh(presc<SC>(Cold[2 * s + 2][1])));
            N1 = pack_h2(fast_tanh(presc<SC>(Cold[2 * s + 2][2])),
                         fast_tanh(presc<SC>(Cold[2 * s + 2][3])));
            N2 = pack_h2(fast_tanh(presc<SC>(Cold[2 * s + 3][0])),
                         fast_tanh(presc<SC>(Cold[2 * s + 3][1])));
            N3 = pack_h2(fast_tanh(presc<SC>(Cold[2 * s + 3][2])),
                         fast_tanh(presc<SC>(Cold[2 * s + 3][3])));
        }
        const uint4* bp = &BL[s * 256 + lane];
#pragma unroll
        for (int jp = 0; jp < 8; jp++) {
            uint4 b = __ldg(bp + jp * 32);
            mma16816(Cnew[2 * jp],     A0, A1, A2, A3, b.x, b.y);
            mma16816(Cnew[2 * jp + 1], A0, A1, A2, A3, b.z, b.w);
        }
        A0 = N0; A1 = N1; A2 = N2; A3 = N3;
    }
}

// ---------------- kernel 3: pipelined fp16 HMMA MLP ------------------------
// sbias layout: [0..127]   bin * 2^10 (input-layer bias, pre-scaled)
//               [128..255] bh[0], [256..383] bh[1], [384..511] bh[2]
__global__ void __launch_bounds__(256, 1) mlp_mma(
    const float* __restrict__ dp_bin, const float* __restrict__ dp_bh,
    const float* __restrict__ dp_Wout, const float* __restrict__ dp_bout,
    const float* __restrict__ ic_bin, const float* __restrict__ ic_bh,
    const float* __restrict__ ic_Wout, const float* __restrict__ ic_bout) {
    __shared__ __align__(8) float sbias[512];
    __shared__ __align__(8) float swout[128];
    const bool isdp = blockIdx.x < DPBLKS;
    const int rowblk = isdp ? blockIdx.x : (blockIdx.x - DPBLKS);
    const float* bin  = isdp ? dp_bin  : ic_bin;
    const float* bh   = isdp ? dp_bh   : ic_bh;
    const float* Wout = isdp ? dp_Wout : ic_Wout;
    const float* bout = isdp ? dp_bout : ic_bout;

    const int tid = threadIdx.x, w = tid >> 5, lane = tid & 31;
    const int q = lane & 3, nr = lane >> 2;

    if (tid < 128) {
        sbias[tid]       = bin[tid] * 1024.0f;   // match input-layer W scale
        sbias[128 + tid] = bh[tid];
        sbias[256 + tid] = bh[128 + tid];
        sbias[384 + tid] = bh[256 + tid];
        swout[tid]       = Wout[tid];
    }
    __syncthreads();

    const int r0 = rowblk * 128 + w * 16 + nr;   // this thread: rows r0, r0+8
    const uint4* __restrict__ BpIn = g_WpIn + (isdp ? 0 : 1) * 512;
    const uint4* __restrict__ BpH  = g_WpH  + (isdp ? 0 : 1) * 6144;

    float CA[16][4], CB[16][4];
    // ---- init CA with input-layer bias (pre-scaled x 2^10) ----
#pragma unroll
    for (int j = 0; j < 16; j++) {
        float2 bb = *(const float2*)(sbias + j * 8 + 2 * q);
        CA[j][0] = bb.x; CA[j][1] = bb.y;
        CA[j][2] = bb.x; CA[j][3] = bb.y;
    }

    // ---- input layer: k8, 3-product fp16 split -> CA (pre-acts x 2^10) ----
    {
        uint32_t a0h, a0l, a1h, a1l;
        build_in(isdp, r0, q, a0h, a0l);
        build_in(isdp, r0 + 8, q, a1h, a1l);
#pragma unroll
        for (int jg = 0; jg < 4; jg++) {
            uint4 b0 = __ldg(&BpIn[(jg * 4 + 0) * 32 + lane]);
            uint4 b1 = __ldg(&BpIn[(jg * 4 + 1) * 32 + lane]);
            uint4 b2 = __ldg(&BpIn[(jg * 4 + 2) * 32 + lane]);
            uint4 b3 = __ldg(&BpIn[(jg * 4 + 3) * 32 + lane]);
            mma1688(CA[jg * 4 + 0], a0h, a1h, b0.x);
            mma1688(CA[jg * 4 + 1], a0h, a1h, b1.x);
            mma1688(CA[jg * 4 + 2], a0h, a1h, b2.x);
            mma1688(CA[jg * 4 + 3], a0h, a1h, b3.x);
            mma1688(CA[jg * 4 + 0], a0h, a1h, b0.z);
            mma1688(CA[jg * 4 + 1], a0h, a1h, b1.z);
            mma1688(CA[jg * 4 + 2], a0h, a1h, b2.z);
            mma1688(CA[jg * 4 + 3], a0h, a1h, b3.z);
            mma1688(CA[jg * 4 + 0], a0l, a1l, b0.x);
            mma1688(CA[jg * 4 + 1], a0l, a1l, b1.x);
            mma1688(CA[jg * 4 + 2], a0l, a1l, b2.x);
            mma1688(CA[jg * 4 + 3], a0l, a1l, b3.x);
        }
    }

    // ---- 3 pipelined hidden layers (bias folded into accumulators) ----
    hidden_layer<true >(CA, CB, sbias + 128, BpH,        lane, q);
    hidden_layer<false>(CB, CA, sbias + 256, BpH + 2048, lane, q);
    hidden_layer<false>(CA, CB, sbias + 384, BpH + 4096, lane, q);

    // ---- final: tanh (bias already inside CB) + dot(Wout) + quad reduce ---
    float s0 = 0.f, s1 = 0.f;
#pragma unroll
    for (int j = 0; j < 16; j++) {
        float2 ww = *(const float2*)(swout + j * 8 + 2 * q);
        s0 = fmaf(fast_tanh(CB[j][0]), ww.x, s0);
        s0 = fmaf(fast_tanh(CB[j][1]), ww.y, s0);
        s1 = fmaf(fast_tanh(CB[j][2]), ww.x, s1);
        s1 = fmaf(fast_tanh(CB[j][3]), ww.y, s1);
    }
    s0 += __shfl_xor_sync(0xffffffffu, s0, 1);
    s0 += __shfl_xor_sync(0xffffffffu, s0, 2);
    s1 += __shfl_xor_sync(0xffffffffu, s1, 1);
    s1 += __shfl_xor_sync(0xffffffffu, s1, 2);
    if (q == 0) {
        float bo = __ldg(bout);
        float* gout = isdp ? g_dp : g_ic;
        gout[r0]     = s0 + bo;
        gout[r0 + 8] = s1 + bo;
    }
}

// ---------------- kernel 4: GL quadrature + final scaling ------------------
__global__ void combine_kernel(float* __restrict__ out) {
    int i = blockIdx.x * blockDim.x + threadIdx.x;
    if (i >= NPTS) return;
    const float* f = g_feats + i * 8;
    float a = f[5], inv = f[4];
    const float w0 = (float)(5.0 / 9.0), w1 = (float)(8.0 / 9.0);
    float s = w0 * g_dp[3 * i] + w1 * g_dp[3 * i + 1] + w0 * g_dp[3 * i + 2];
    out[i] = (g_ic[i] + a * s) * inv;
}

// ---------------- host launcher --------------------------------------------
extern "C" void kernel_launch(void* const* d_in, const int* in_sizes, int n_in,
                              void* d_out, int out_size) {
    const float* tx      = (const float*)d_in[0];
    const float* dp_Win  = (const float*)d_in[1];
    const float* dp_bin  = (const float*)d_in[2];
    const float* dp_Wh   = (const float*)d_in[3];
    const float* dp_bh   = (const float*)d_in[4];
    const float* dp_Wout = (const float*)d_in[5];
    const float* dp_bout = (const float*)d_in[6];
    const float* ic_Win  = (const float*)d_in[7];
    const float* ic_bin  = (const float*)d_in[8];
    const float* ic_Wh   = (const float*)d_in[9];
    const float* ic_bh   = (const float*)d_in[10];
    const float* ic_Wout = (const float*)d_in[11];
    const float* ic_bout = (const float*)d_in[12];
    float* out = (float*)d_out;

    prep_kernel<<<NPTS / 256, 256>>>((const float4*)tx);
    wprep_kernel<<<(1024 + 2 * 6144 + 255) / 256, 256>>>(dp_Win, dp_Wh,
                                                         ic_Win, ic_Wh);
    mlp_mma<<<DPBLKS + ICBLKS, 256>>>(dp_bin, dp_bh, dp_Wout, dp_bout,
                                      ic_bin, ic_bh, ic_Wout, ic_bout);
    combine_kernel<<<NPTS / 256, 256>>>(out);
}

// round 17
// speedup vs baseline: 1.0403x; 1.0148x over previous
#include <cuda_runtime.h>
#include <cuda_fp16.h>
#include <cstdint>

#define NPTS 262144
#define DPBLKS 6144   // 3*NPTS/128
#define ICBLKS 2048   // NPTS/128

// ---------------- scratch (__device__ globals; no allocation allowed) -----
__device__ float g_feats[NPTS * 8];   // [r, ux, uy, uz, inv, a, 0, 0]
__device__ float g_ic[NPTS];
__device__ float g_dp[NPTS * 3];
__device__ float g_sink;              // skew-chain sink (never actually hit)

// Input layer B frags (3-product split, weights pre-scaled 2^10):
//   per MLP 16 frags x 32 lanes, uint4 {h0, h1, l0, l1}
__device__ uint4 g_WpIn[2 * 512];
// Hidden layer B frags (single fp16, unscaled), two n8 frags per uint4:
//   per MLP 24 ksteps x 8 jpairs x 32 lanes, uint4 {j0b0, j0b1, j1b0, j1b1}
__device__ uint4 g_WpH[2 * 6144];

__constant__ float c_np1[3] = {1.0f - 0.7745966692f, 1.0f, 1.0f + 0.7745966692f};

#define WSI 0.0009765625f   // 2^-10: undo input-layer weight pre-scale

// ---------------- math helpers --------------------------------------------
// single-instruction HW tanh (MUFU), fp32 — R14-validated accuracy
__device__ __forceinline__ float fast_tanh(float x) {
    float t;
    asm("tanh.approx.f32 %0, %1;" : "=f"(t) : "f"(x));
    return t;
}
// pack two floats into fp16x2 (v0 -> low half)
__device__ __forceinline__ uint32_t pack_h2(float v0, float v1) {
    uint32_t u;
    asm("cvt.rn.f16x2.f32 %0, %1, %2;" : "=r"(u) : "f"(v1), "f"(v0));
    return u;
}
// split (v0,v1) into fp16x2 hi + fp16x2 residual lo
__device__ __forceinline__ void split2h(float v0, float v1,
                                        uint32_t& uh, uint32_t& ul) {
    __half h0 = __float2half_rn(v0), h1 = __float2half_rn(v1);
    __half l0 = __float2half_rn(v0 - __half2float(h0));
    __half l1 = __float2half_rn(v1 - __half2float(h1));
    uh = (uint32_t)__half_as_ushort(h0) | ((uint32_t)__half_as_ushort(h1) << 16);
    ul = (uint32_t)__half_as_ushort(l0) | ((uint32_t)__half_as_ushort(l1) << 16);
}

// fp16 HMMA k16: D(16x8) += A(16x16) * B(16x8), fp32 accum
__device__ __forceinline__ void mma16816(float c[4], uint32_t a0, uint32_t a1,
                                         uint32_t a2, uint32_t a3,
                                         uint32_t b0, uint32_t b1) {
    asm volatile(
        "mma.sync.aligned.m16n8k16.row.col.f32.f16.f16.f32 "
        "{%0,%1,%2,%3}, {%4,%5,%6,%7}, {%8,%9}, {%0,%1,%2,%3};"
        : "+f"(c[0]), "+f"(c[1]), "+f"(c[2]), "+f"(c[3])
        : "r"(a0), "r"(a1), "r"(a2), "r"(a3), "r"(b0), "r"(b1));
}
// fp16 HMMA k8 (input layer)
__device__ __forceinline__ void mma1688(float c[4], uint32_t a0, uint32_t a1,
                                        uint32_t b0) {
    asm volatile(
        "mma.sync.aligned.m16n8k8.row.col.f32.f16.f16.f32 "
        "{%0,%1,%2,%3}, {%4,%5}, {%6}, {%0,%1,%2,%3};"
        : "+f"(c[0]), "+f"(c[1]), "+f"(c[2]), "+f"(c[3])
        : "r"(a0), "r"(a1), "r"(b0));
}

// ---------------- kernel 1: per-point features ----------------------------
__global__ void prep_kernel(const float4* __restrict__ tx) {
    int i = blockIdx.x * blockDim.x + threadIdx.x;
    if (i >= NPTS) return;
    float4 v = tx[i];
    float r = sqrtf(v.y * v.y + v.z * v.z + v.w * v.w);
    float rs = fmaxf(r, 1e-8f);
    float inv = 1.0f / (1.0f + r);
    float a = v.x * 0.5f;   // T0 = 0; CLIP = 1 -> min(r, max r) == r
    float* o = g_feats + i * 8;
    ((float4*)o)[0] = make_float4(r, v.y / rs, v.z / rs, v.w / rs);
    ((float4*)o)[1] = make_float4(inv, a, 0.f, 0.f);
}

// ---------------- kernel 2: pack weights ----------------------------------
__global__ void wprep_kernel(const float* __restrict__ dp_Win,
                             const float* __restrict__ dp_Wh,
                             const float* __restrict__ ic_Win,
                             const float* __restrict__ ic_Wh) {
    int t = blockIdx.x * blockDim.x + threadIdx.x;
    if (t < 1024) {
        // ---- input layer: hi/lo split, weights x 2^10 ----
        int m = t >> 9;                 // 0 = dp, 1 = ic
        int e = t & 511;
        int J = e >> 5, lane = e & 31;
        const float* Win = m ? ic_Win : dp_Win;
        int din = m ? 5 : 6;
        int q = lane & 3;
        int n = J * 8 + (lane >> 2);
        int k0 = 2 * q;
        float w00 = (k0     < din) ? Win[k0 * 128 + n]       : 0.f;
        float w01 = (k0 + 1 < din) ? Win[(k0 + 1) * 128 + n] : 0.f;
        uint32_t h0, l0;
        split2h(w00 * 1024.0f, w01 * 1024.0f, h0, l0);
        g_WpIn[t] = make_uint4(h0, 0u, l0, 0u);
        return;
    }
    int t2 = t - 1024;
    if (t2 >= 2 * 6144) return;
    // ---- hidden layers: single fp16, two j-frags per uint4 ----
    int m = t2 / 6144;
    int e = t2 - m * 6144;
    int lane = e & 31;
    int jp = (e >> 5) & 7;
    int ks = e >> 8;                    // 0..23
    int l = ks >> 3, s = ks & 7;
    const float* W = (m ? ic_Wh : dp_Wh) + l * 16384;
    int q = lane & 3;
    int kb = 16 * s + 2 * q;
    int nrow = lane >> 2;

    int n0 = (2 * jp) * 8 + nrow;
    uint32_t j0b0 = pack_h2(W[kb * 128 + n0],       W[(kb + 1) * 128 + n0]);
    uint32_t j0b1 = pack_h2(W[(kb + 8) * 128 + n0], W[(kb + 9) * 128 + n0]);
    int n1 = (2 * jp + 1) * 8 + nrow;
    uint32_t j1b0 = pack_h2(W[kb * 128 + n1],       W[(kb + 1) * 128 + n1]);
    uint32_t j1b1 = pack_h2(W[(kb + 8) * 128 + n1], W[(kb + 9) * 128 + n1]);
    g_WpH[t2] = make_uint4(j0b0, j0b1, j1b0, j1b1);
}

// ---------------- input A-fragment builder (fp16 split) --------------------
__device__ __forceinline__ void build_in(bool isdp, int grow, int q,
                                         uint32_t& ah, uint32_t& al) {
    float xa, xb;
    if (isdp) {
        int p = grow / 3, nd = grow - 3 * p;
        float4 f0 = *(const float4*)(g_feats + p * 8);       // r ux uy uz
        float2 f1 = *(const float2*)(g_feats + p * 8 + 4);   // inv a
        float tt = f1.y * c_np1[nd];
        xa = (q == 0) ? tt   : (q == 1) ? f0.y : (q == 2) ? f0.w : 0.f;
        xb = (q == 0) ? f0.x : (q == 1) ? f0.z : (q == 2) ? f1.x : 0.f;
    } else {
        float4 f0 = *(const float4*)(g_feats + grow * 8);
        float2 f1 = *(const float2*)(g_feats + grow * 8 + 4);
        xa = (q == 0) ? f0.x : (q == 1) ? f0.z : (q == 2) ? f1.x : 0.f;
        xb = (q == 0) ? f0.y : (q == 1) ? f0.w : 0.f;
    }
    split2h(xa, xb, ah, al);
}

// ---------------- one pipelined hidden layer -------------------------------
// Consumes Cold (pre-activations of previous layer), produces Cnew.
// Epilogue for k-step s+1 is interleaved with the HMMAs of k-step s.
__device__ __forceinline__ void hidden_layer(
    const float (&Cold)[16][4], float (&Cnew)[16][4],
    const float* __restrict__ biasl, float sc,
    const uint4* __restrict__ BL, int lane, int q) {
#pragma unroll
    for (int j = 0; j < 16; j++) {
        Cnew[j][0] = 0.f; Cnew[j][1] = 0.f; Cnew[j][2] = 0.f; Cnew[j][3] = 0.f;
    }
    uint32_t A0, A1, A2, A3;
    {   // epilogue for s = 0 (j = 0,1)
        float2 b0 = *(const float2*)(biasl + 0 * 8 + 2 * q);
        float2 b1 = *(const float2*)(biasl + 1 * 8 + 2 * q);
        A0 = pack_h2(fast_tanh(fmaf(Cold[0][0], sc, b0.x)),
                     fast_tanh(fmaf(Cold[0][1], sc, b0.y)));
        A1 = pack_h2(fast_tanh(fmaf(Cold[0][2], sc, b0.x)),
                     fast_tanh(fmaf(Cold[0][3], sc, b0.y)));
        A2 = pack_h2(fast_tanh(fmaf(Cold[1][0], sc, b1.x)),
                     fast_tanh(fmaf(Cold[1][1], sc, b1.y)));
        A3 = pack_h2(fast_tanh(fmaf(Cold[1][2], sc, b1.x)),
                     fast_tanh(fmaf(Cold[1][3], sc, b1.y)));
    }
#pragma unroll
    for (int s = 0; s < 8; s++) {
        uint32_t N0 = 0, N1 = 0, N2 = 0, N3 = 0;
        if (s < 7) {   // epilogue for s+1 — independent of this step's MMAs
            float2 b0 = *(const float2*)(biasl + (2 * s + 2) * 8 + 2 * q);
            float2 b1 = *(const float2*)(biasl + (2 * s + 3) * 8 + 2 * q);
            N0 = pack_h2(fast_tanh(fmaf(Cold[2 * s + 2][0], sc, b0.x)),
                         fast_tanh(fmaf(Cold[2 * s + 2][1], sc, b0.y)));
            N1 = pack_h2(fast_tanh(fmaf(Cold[2 * s + 2][2], sc, b0.x)),
                         fast_tanh(fmaf(Cold[2 * s + 2][3], sc, b0.y)));
            N2 = pack_h2(fast_tanh(fmaf(Cold[2 * s + 3][0], sc, b1.x)),
                         fast_tanh(fmaf(Cold[2 * s + 3][1], sc, b1.y)));
            N3 = pack_h2(fast_tanh(fmaf(Cold[2 * s + 3][2], sc, b1.x)),
                         fast_tanh(fmaf(Cold[2 * s + 3][3], sc, b1.y)));
        }
        const uint4* bp = &BL[s * 256 + lane];
#pragma unroll
        for (int jp = 0; jp < 8; jp++) {
            uint4 b = __ldg(bp + jp * 32);
            mma16816(Cnew[2 * jp],     A0, A1, A2, A3, b.x, b.y);
            mma16816(Cnew[2 * jp + 1], A0, A1, A2, A3, b.z, b.w);
        }
        A0 = N0; A1 = N1; A2 = N2; A3 = N3;
    }
}

// ---------------- kernel 3: pipelined fp16 HMMA MLP + warp phase-skew ------
__global__ void __launch_bounds__(256, 1) mlp_mma(
    const float* __restrict__ dp_bin, const float* __restrict__ dp_bh,
    const float* __restrict__ dp_Wout, const float* __restrict__ dp_bout,
    const float* __restrict__ ic_bin, const float* __restrict__ ic_bh,
    const float* __restrict__ ic_Wout, const float* __restrict__ ic_bout) {
    __shared__ __align__(8) float sbias[512];
    __shared__ __align__(8) float swout[128];
    const bool isdp = blockIdx.x < DPBLKS;
    const int rowblk = isdp ? blockIdx.x : (blockIdx.x - DPBLKS);
    const float* bin  = isdp ? dp_bin  : ic_bin;
    const float* bh   = isdp ? dp_bh   : ic_bh;
    const float* Wout = isdp ? dp_Wout : ic_Wout;
    const float* bout = isdp ? dp_bout : ic_bout;

    const int tid = threadIdx.x, w = tid >> 5, lane = tid & 31;
    const int q = lane & 3, nr = lane >> 2;

    if (tid < 128) {
        sbias[tid]       = bin[tid];
        sbias[128 + tid] = bh[tid];
        sbias[256 + tid] = bh[128 + tid];
        sbias[384 + tid] = bh[256 + tid];
        swout[tid]       = Wout[tid];
    }
    __syncthreads();

    // ---- phase-skew: warps 4-7 (co-resident with 0-3 on the same SMSPs)
    // run a ~600-cycle dependent FMA chain so that their MUFU-heavy epilogue
    // phases anti-align with warps 0-3's tensor-heavy MMA phases.
    if (w >= 4) {
        float d = sbias[tid & 127];
#pragma unroll
        for (int it = 0; it < 150; it++)
            d = fmaf(d, 1.0000001f, 1.0e-30f);
        if (__float_as_uint(d) == 0xDEADBEEFu) g_sink = d;   // never taken
    }

    const int r0 = rowblk * 128 + w * 16 + nr;   // this thread: rows r0, r0+8
    const uint4* __restrict__ BpIn = g_WpIn + (isdp ? 0 : 1) * 512;
    const uint4* __restrict__ BpH  = g_WpH  + (isdp ? 0 : 1) * 6144;

    float CA[16][4], CB[16][4];
#pragma unroll
    for (int j = 0; j < 16; j++) {
        CA[j][0] = 0.f; CA[j][1] = 0.f; CA[j][2] = 0.f; CA[j][3] = 0.f;
    }

    // ---- input layer: k8, 3-product fp16 split -> CA (pre-acts x 2^10) ----
    {
        uint32_t a0h, a0l, a1h, a1l;
        build_in(isdp, r0, q, a0h, a0l);
        build_in(isdp, r0 + 8, q, a1h, a1l);
#pragma unroll
        for (int jg = 0; jg < 4; jg++) {
            uint4 b0 = __ldg(&BpIn[(jg * 4 + 0) * 32 + lane]);
            uint4 b1 = __ldg(&BpIn[(jg * 4 + 1) * 32 + lane]);
            uint4 b2 = __ldg(&BpIn[(jg * 4 + 2) * 32 + lane]);
            uint4 b3 = __ldg(&BpIn[(jg * 4 + 3) * 32 + lane]);
            mma1688(CA[jg * 4 + 0], a0h, a1h, b0.x);
            mma1688(CA[jg * 4 + 1], a0h, a1h, b1.x);
            mma1688(CA[jg * 4 + 2], a0h, a1h, b2.x);
            mma1688(CA[jg * 4 + 3], a0h, a1h, b3.x);
            mma1688(CA[jg * 4 + 0], a0h, a1h, b0.z);
            mma1688(CA[jg * 4 + 1], a0h, a1h, b1.z);
            mma1688(CA[jg * 4 + 2], a0h, a1h, b2.z);
            mma1688(CA[jg * 4 + 3], a0h, a1h, b3.z);
            mma1688(CA[jg * 4 + 0], a0l, a1l, b0.x);
            mma1688(CA[jg * 4 + 1], a0l, a1l, b1.x);
            mma1688(CA[jg * 4 + 2], a0l, a1l, b2.x);
            mma1688(CA[jg * 4 + 3], a0l, a1l, b3.x);
        }
    }

    // ---- 3 pipelined hidden layers ----
    hidden_layer(CA, CB, sbias,       WSI,  BpH,        lane, q);
    hidden_layer(CB, CA, sbias + 128, 1.0f, BpH + 2048, lane, q);
    hidden_layer(CA, CB, sbias + 256, 1.0f, BpH + 4096, lane, q);

    // ---- final: bias + fp32 tanh + dot(Wout) + quad reduce ----
    float s0 = 0.f, s1 = 0.f;
#pragma unroll
    for (int j = 0; j < 16; j++) {
        float2 bb = *(const float2*)(sbias + 384 + j * 8 + 2 * q);
        float2 ww = *(const float2*)(swout + j * 8 + 2 * q);
        s0 = fmaf(fast_tanh(CB[j][0] + bb.x), ww.x, s0);
        s0 = fmaf(fast_tanh(CB[j][1] + bb.y), ww.y, s0);
        s1 = fmaf(fast_tanh(CB[j][2] + bb.x), ww.x, s1);
        s1 = fmaf(fast_tanh(CB[j][3] + bb.y), ww.y, s1);
    }
    s0 += __shfl_xor_sync(0xffffffffu, s0, 1);
    s0 += __shfl_xor_sync(0xffffffffu, s0, 2);
    s1 += __shfl_xor_sync(0xffffffffu, s1, 1);
    s1 += __shfl_xor_sync(0xffffffffu, s1, 2);
    if (q == 0) {
        float bo = __ldg(bout);
        float* gout = isdp ? g_dp : g_ic;
        gout[r0]     = s0 + bo;
        gout[r0 + 8] = s1 + bo;
    }
}

// ---------------- kernel 4: GL quadrature + final scaling ------------------
__global__ void combine_kernel(float* __restrict__ out) {
    int i = blockIdx.x * blockDim.x + threadIdx.x;
    if (i >= NPTS) return;
    const float* f = g_feats + i * 8;
    float a = f[5], inv = f[4];
    const float w0 = (float)(5.0 / 9.0), w1 = (float)(8.0 / 9.0);
    float s = w0 * g_dp[3 * i] + w1 * g_dp[3 * i + 1] + w0 * g_dp[3 * i + 2];
    out[i] = (g_ic[i] + a * s) * inv;
}

// ---------------- host launcher --------------------------------------------
extern "C" void kernel_launch(void* const* d_in, const int* in_sizes, int n_in,
                              void* d_out, int out_size) {
    const float* tx      = (const float*)d_in[0];
    const float* dp_Win  = (const float*)d_in[1];
    const float* dp_bin  = (const float*)d_in[2];
    const float* dp_Wh   = (const float*)d_in[3];
    const float* dp_bh   = (const float*)d_in[4];
    const float* dp_Wout = (const float*)d_in[5];
    const float* dp_bout = (const float*)d_in[6];
    const float* ic_Win  = (const float*)d_in[7];
    const float* ic_bin  = (const float*)d_in[8];
    const float* ic_Wh   = (const float*)d_in[9];
    const float* ic_bh   = (const float*)d_in[10];
    const float* ic_Wout = (const float*)d_in[11];
    const float* ic_bout = (const float*)d_in[12];
    float* out = (float*)d_out;

    prep_kernel<<<NPTS / 256, 256>>>((const float4*)tx);
    wprep_kernel<<<(1024 + 2 * 6144 + 255) / 256, 256>>>(dp_Win, dp_Wh,
                                                         ic_Win, ic_Wh);
    mlp_mma<<<DPBLKS + ICBLKS, 256>>>(dp_bin, dp_bh, dp_Wout, dp_bout,
                                      ic_bin, ic_bh, ic_Wout, ic_bout);
    combine_kernel<<<NPTS / 256, 256>>>(out);
}